// round 15
// baseline (speedup 1.0000x reference)
#include <cuda_runtime.h>
#include <cuda_fp16.h>
#include <math.h>
#include <stdint.h>

#define N_NODES   50000
#define N_EDGES   800000
#define IN_DIM    128
#define OUT_DIM   64
#define NEG_SLOPE 0.01f

// ---------------- scratch (static device globals; no allocation) ------------
__device__ __align__(16) uint32_t g_zh[N_NODES * 32];  // z rows as half2 pairs (128B/row)
__device__ __align__(16) float    g_w[N_EDGES];        // per-edge exp(lrelu(e))
__device__ __align__(16) uint32_t g_wfrag[8 * 16 * 32 * 2];  // prebuilt tf32 B fragments (8192 u32)
__device__ float g_s[N_NODES];             // z[n] . a_src
__device__ float g_d[N_NODES];             // z[n] . a_dst
__device__ int   g_rs[N_NODES + 1];        // row_start per dst node (dst sorted)

__device__ __forceinline__ uint32_t f2tf32(float x) {
    uint32_t u;
    asm("cvt.rna.tf32.f32 %0, %1;" : "=r"(u) : "f"(x));
    return u;
}
__device__ __forceinline__ float2 h2f2(uint32_t u) {
    return __half22float2(*(const __half2*)&u);
}

// ---------------------------------------------------------------------------
// K0: one-shot B-fragment build (fw -> tf32 mma fragments), 4096 threads.
// ---------------------------------------------------------------------------
__global__ __launch_bounds__(256) void wfrag_build_kernel(const float* __restrict__ fw) {
    const int idx = blockIdx.x * blockDim.x + threadIdx.x;   // 0..4095
    if (idx >= 8 * 16 * 32) return;
    const int lane = idx & 31;
    const int kt   = (idx >> 5) & 15;
    const int nt   = idx >> 9;
    const int n = nt * 8 + (lane >> 2);
    const int k = kt * 8 + (lane & 3);
    uint2 p;
    p.x = f2tf32(fw[n * IN_DIM + k]);
    p.y = f2tf32(fw[n * IN_DIM + k + 4]);
    *(uint2*)&g_wfrag[2 * idx] = p;
}

// ---------------------------------------------------------------------------
// K1: z = h @ fc_w^T via tf32 mma.sync.m16n8k8; fused s/d epilogue;
// z stored as fp16. BM=128 -> 391 blocks = single wave. 8 warps;
// warp w owns rows w*16..+15 x all 64 cols. K chunks of 16, reg double-buffer.
// ---------------------------------------------------------------------------
#define GEMM_BM 128
#define HS 20   // row stride in u32 (16 + 4 pad): conflict-free scalar LDS

__global__ __launch_bounds__(256) void gemm_sd_kernel(const float* __restrict__ h,
                                                      const float* __restrict__ attn_w) {
    __shared__ uint32_t wfrag[8 * 16 * 32 * 2];   // 32 KB (2048 uint4)
    __shared__ uint32_t hs[GEMM_BM * HS];         // 10 KB: h K-chunk (tf32 bits)
    __shared__ float a_srcs[OUT_DIM];
    __shared__ float a_dsts[OUT_DIM];

    const int t    = threadIdx.x;
    const int wid  = t >> 5;
    const int lane = t & 31;
    const int gid  = lane >> 2;   // 0..7
    const int tid  = lane & 3;    // 0..3
    const int mrow = wid * 16;    // warp's row tile

#pragma unroll
    for (int i = 0; i < 8; i++) {
        int idx = i * 256 + t;
        ((uint4*)wfrag)[idx] = ((const uint4*)g_wfrag)[idx];
    }
    if (t < OUT_DIM)            a_srcs[t]           = attn_w[t];
    else if (t < 2 * OUT_DIM)   a_dsts[t - OUT_DIM] = attn_w[t];

    const int node0 = blockIdx.x * GEMM_BM;
    const int r0 = node0 + mrow + gid;
    const int r1 = r0 + 8;
    const bool v0 = (r0 < N_NODES);
    const bool v1 = (r1 < N_NODES);

    const int n_a = t >> 2,         kq_a = t & 3;
    const int n_b = (t + 256) >> 2, kq_b = (t + 256) & 3;
    const int gn_a = node0 + n_a,   gn_b = node0 + n_b;
    const bool va = (gn_a < N_NODES), vb = (gn_b < N_NODES);
    const float* pa = h + (size_t)gn_a * IN_DIM + kq_a * 4;
    const float* pb = h + (size_t)gn_b * IN_DIM + kq_b * 4;

    float4 bufa, bufb;
    bufa = va ? *(const float4*)(pa) : make_float4(0.f, 0.f, 0.f, 0.f);
    bufb = vb ? *(const float4*)(pb) : make_float4(0.f, 0.f, 0.f, 0.f);

    float acc[8][4];
#pragma unroll
    for (int nt = 0; nt < 8; nt++)
#pragma unroll
        for (int c = 0; c < 4; c++) acc[nt][c] = 0.f;

#pragma unroll
    for (int kc = 0; kc < 8; kc++) {
        __syncthreads();
        {
            uint4 u;
            u.x = f2tf32(bufa.x); u.y = f2tf32(bufa.y);
            u.z = f2tf32(bufa.z); u.w = f2tf32(bufa.w);
            *(uint4*)&hs[n_a * HS + kq_a * 4] = u;
            u.x = f2tf32(bufb.x); u.y = f2tf32(bufb.y);
            u.z = f2tf32(bufb.z); u.w = f2tf32(bufb.w);
            *(uint4*)&hs[n_b * HS + kq_b * 4] = u;
        }
        __syncthreads();
        if (kc < 7) {
            const int kb = (kc + 1) * 16;
            bufa = va ? *(const float4*)(pa + kb) : make_float4(0.f, 0.f, 0.f, 0.f);
            bufb = vb ? *(const float4*)(pb + kb) : make_float4(0.f, 0.f, 0.f, 0.f);
        }

#pragma unroll
        for (int kt = 0; kt < 2; kt++) {
            const int k   = kt * 8 + tid;
            const int ktg = kc * 2 + kt;
            uint32_t a0 = hs[(mrow + gid)     * HS + k];
            uint32_t a1 = hs[(mrow + gid + 8) * HS + k];
            uint32_t a2 = hs[(mrow + gid)     * HS + k + 4];
            uint32_t a3 = hs[(mrow + gid + 8) * HS + k + 4];
#pragma unroll
            for (int nt = 0; nt < 8; nt++) {
                int base = ((nt * 16 + ktg) * 32 + lane) * 2;
                uint32_t b0 = wfrag[base];
                uint32_t b1 = wfrag[base + 1];
                asm volatile(
                    "mma.sync.aligned.m16n8k8.row.col.f32.tf32.tf32.f32 "
                    "{%0,%1,%2,%3}, {%4,%5,%6,%7}, {%8,%9}, {%0,%1,%2,%3};"
                    : "+f"(acc[nt][0]), "+f"(acc[nt][1]),
                      "+f"(acc[nt][2]), "+f"(acc[nt][3])
                    : "r"(a0), "r"(a1), "r"(a2), "r"(a3), "r"(b0), "r"(b1));
            }
        }
    }

    float s0 = 0.f, d0 = 0.f, s1 = 0.f, d1 = 0.f;
#pragma unroll
    for (int nt = 0; nt < 8; nt++) {
        int col = nt * 8 + tid * 2;
        if (v0) {
            __half2 p = __float22half2_rn(make_float2(acc[nt][0], acc[nt][1]));
            g_zh[(size_t)r0 * 32 + (col >> 1)] = *(uint32_t*)&p;
        }
        if (v1) {
            __half2 p = __float22half2_rn(make_float2(acc[nt][2], acc[nt][3]));
            g_zh[(size_t)r1 * 32 + (col >> 1)] = *(uint32_t*)&p;
        }
        float as0 = a_srcs[col], as1 = a_srcs[col + 1];
        float ad0 = a_dsts[col], ad1 = a_dsts[col + 1];
        s0 += acc[nt][0] * as0 + acc[nt][1] * as1;
        d0 += acc[nt][0] * ad0 + acc[nt][1] * ad1;
        s1 += acc[nt][2] * as0 + acc[nt][3] * as1;
        d1 += acc[nt][2] * ad0 + acc[nt][3] * ad1;
    }
#pragma unroll
    for (int o = 1; o <= 2; o <<= 1) {
        s0 += __shfl_xor_sync(0xffffffffu, s0, o);
        d0 += __shfl_xor_sync(0xffffffffu, d0, o);
        s1 += __shfl_xor_sync(0xffffffffu, s1, o);
        d1 += __shfl_xor_sync(0xffffffffu, d1, o);
    }
    if (tid == 0) {
        if (v0) { g_s[r0] = s0; g_d[r0] = d0; }
        if (v1) { g_s[r1] = s1; g_d[r1] = d1; }
    }
}

// ---------------------------------------------------------------------------
// K2: fused edge-weight precompute + rowstart scan. 4 edges/thread.
// ---------------------------------------------------------------------------
#define WR_EPT     4
#define WR_THREADS (N_EDGES / WR_EPT)   // 200000

__global__ __launch_bounds__(256) void wgt_rs_kernel(const int* __restrict__ src,
                                                     const int* __restrict__ dst) {
    const int gtid = blockIdx.x * blockDim.x + threadIdx.x;
    if (gtid >= WR_THREADS) return;
    const int i0 = gtid * WR_EPT;

    int4 s4 = *(const int4*)(src + i0);
    int4 d4 = *(const int4*)(dst + i0);

    float4 w;
    {
        float e0 = g_s[s4.x] + g_d[d4.x]; e0 = (e0 > 0.f) ? e0 : NEG_SLOPE * e0;
        float e1 = g_s[s4.y] + g_d[d4.y]; e1 = (e1 > 0.f) ? e1 : NEG_SLOPE * e1;
        float e2 = g_s[s4.z] + g_d[d4.z]; e2 = (e2 > 0.f) ? e2 : NEG_SLOPE * e2;
        float e3 = g_s[s4.w] + g_d[d4.w]; e3 = (e3 > 0.f) ? e3 : NEG_SLOPE * e3;
        w = make_float4(__expf(e0), __expf(e1), __expf(e2), __expf(e3));
    }
    *(float4*)(g_w + i0) = w;

    int prev = __shfl_up_sync(0xffffffffu, d4.w, 1);
    if ((threadIdx.x & 31) == 0) prev = (i0 == 0) ? -1 : dst[i0 - 1];

    int p = prev;
    int dk[4] = {d4.x, d4.y, d4.z, d4.w};
#pragma unroll
    for (int k = 0; k < WR_EPT; k++) {
        for (int n = p + 1; n <= dk[k]; n++) g_rs[n] = i0 + k;
        p = dk[k];
    }
    if (i0 + WR_EPT == N_EDGES) {
        for (int n = d4.w + 1; n <= N_NODES; n++) g_rs[n] = N_EDGES;
    }
}

// ---------------------------------------------------------------------------
// K4: aggregation, one warp per dst node, precomputed weights.
// 16-edge SUPERPACKETS: all 4 w + 4 src + 4 z-row gathers issued before any
// compute (deep MLP); guarded 8-packet loop mops the tail.
// ---------------------------------------------------------------------------
__global__ __launch_bounds__(256) void edge_agg_kernel(const int* __restrict__ src,
                                                       float* __restrict__ out) {
    const int n    = (blockIdx.x * blockDim.x + threadIdx.x) >> 5;
    const int lane = threadIdx.x & 31;
    const int g    = lane >> 3;   // edge slot within packet
    const int q    = lane & 7;    // column quad: cols q*8 .. q*8+7
    if (n >= N_NODES) return;

    const int beg = g_rs[n], end = g_rs[n + 1];
    const uint4* zr = (const uint4*)g_zh;   // 8 uint4 per z row

    float acc[8];
#pragma unroll
    for (int c = 0; c < 8; c++) acc[c] = 0.f;
    float den = 0.f;

    // ---- fast path: 16-edge superpackets, loads batched before compute ------
    int j = beg;
    const int super_end = beg + ((end - beg) & ~15);
    for (; j < super_end; j += 16) {
        const int e0 = j + g, e1 = j + 4 + g, e2 = j + 8 + g, e3 = j + 12 + g;
        const float w0 = g_w[e0], w1 = g_w[e1], w2 = g_w[e2], w3 = g_w[e3];
        const int s0 = __ldg(&src[e0]);
        const int s1 = __ldg(&src[e1]);
        const int s2 = __ldg(&src[e2]);
        const int s3 = __ldg(&src[e3]);
        uint4 A = zr[(size_t)s0 * 8 + q];
        uint4 B = zr[(size_t)s1 * 8 + q];
        uint4 C = zr[(size_t)s2 * 8 + q];
        uint4 D = zr[(size_t)s3 * 8 + q];

        float2 f;
        f = h2f2(A.x); acc[0] += w0 * f.x; acc[1] += w0 * f.y;
        f = h2f2(A.y); acc[2] += w0 * f.x; acc[3] += w0 * f.y;
        f = h2f2(A.z); acc[4] += w0 * f.x; acc[5] += w0 * f.y;
        f = h2f2(A.w); acc[6] += w0 * f.x; acc[7] += w0 * f.y;
        f = h2f2(B.x); acc[0] += w1 * f.x; acc[1] += w1 * f.y;
        f = h2f2(B.y); acc[2] += w1 * f.x; acc[3] += w1 * f.y;
        f = h2f2(B.z); acc[4] += w1 * f.x; acc[5] += w1 * f.y;
        f = h2f2(B.w); acc[6] += w1 * f.x; acc[7] += w1 * f.y;
        f = h2f2(C.x); acc[0] += w2 * f.x; acc[1] += w2 * f.y;
        f = h2f2(C.y); acc[2] += w2 * f.x; acc[3] += w2 * f.y;
        f = h2f2(C.z); acc[4] += w2 * f.x; acc[5] += w2 * f.y;
        f = h2f2(C.w); acc[6] += w2 * f.x; acc[7] += w2 * f.y;
        f = h2f2(D.x); acc[0] += w3 * f.x; acc[1] += w3 * f.y;
        f = h2f2(D.y); acc[2] += w3 * f.x; acc[3] += w3 * f.y;
        f = h2f2(D.z); acc[4] += w3 * f.x; acc[5] += w3 * f.y;
        f = h2f2(D.w); acc[6] += w3 * f.x; acc[7] += w3 * f.y;
        den += (w0 + w1) + (w2 + w3);
    }

    // ---- tail: guarded 8-packets (<=1 full + 1 partial) ---------------------
    for (; j < end; j += 8) {
        const int e0 = j + g;
        const int e1 = j + 4 + g;
        const int i0 = min(e0, end - 1);
        const int i1 = min(e1, end - 1);
        const float w0 = (e0 < end) ? g_w[i0] : 0.f;
        const float w1 = (e1 < end) ? g_w[i1] : 0.f;
        const int   s0 = __ldg(&src[i0]);
        const int   s1 = __ldg(&src[i1]);

        uint4 A = zr[(size_t)s0 * 8 + q];
        uint4 B = zr[(size_t)s1 * 8 + q];
        float2 f;
        f = h2f2(A.x); acc[0] += w0 * f.x; acc[1] += w0 * f.y;
        f = h2f2(A.y); acc[2] += w0 * f.x; acc[3] += w0 * f.y;
        f = h2f2(A.z); acc[4] += w0 * f.x; acc[5] += w0 * f.y;
        f = h2f2(A.w); acc[6] += w0 * f.x; acc[7] += w0 * f.y;
        f = h2f2(B.x); acc[0] += w1 * f.x; acc[1] += w1 * f.y;
        f = h2f2(B.y); acc[2] += w1 * f.x; acc[3] += w1 * f.y;
        f = h2f2(B.z); acc[4] += w1 * f.x; acc[5] += w1 * f.y;
        f = h2f2(B.w); acc[6] += w1 * f.x; acc[7] += w1 * f.y;
        den += w0 + w1;
    }

#pragma unroll
    for (int c = 0; c < 8; c++) {
        acc[c] += __shfl_xor_sync(0xffffffffu, acc[c], 8);
        acc[c] += __shfl_xor_sync(0xffffffffu, acc[c], 16);
    }
    den += __shfl_xor_sync(0xffffffffu, den, 8);
    den += __shfl_xor_sync(0xffffffffu, den, 16);

    if (g == 0) {
        const float inv = (end > beg) ? 1.f / den : 0.f;
        float4* out4 = (float4*)out;
        out4[(size_t)n * 16 + q * 2]     =
            make_float4(acc[0] * inv, acc[1] * inv, acc[2] * inv, acc[3] * inv);
        out4[(size_t)n * 16 + q * 2 + 1] =
            make_float4(acc[4] * inv, acc[5] * inv, acc[6] * inv, acc[7] * inv);
    }
}

// ---------------------------------------------------------------------------
extern "C" void kernel_launch(void* const* d_in, const int* in_sizes, int n_in,
                              void* d_out, int out_size) {
    const float* h      = (const float*)d_in[0];
    const int*   src    = (const int*)d_in[1];
    const int*   dst    = (const int*)d_in[2];
    const float* fc_w   = (const float*)d_in[3];
    const float* attn_w = (const float*)d_in[4];
    float*       out    = (float*)d_out;

    (void)in_sizes; (void)n_in; (void)out_size;

    wfrag_build_kernel<<<16, 256>>>(fc_w);
    gemm_sd_kernel<<<(N_NODES + GEMM_BM - 1) / GEMM_BM, 256>>>(h, attn_w);
    wgt_rs_kernel<<<(WR_THREADS + 255) / 256, 256>>>(src, dst);
    edge_agg_kernel<<<(N_NODES * 32 + 255) / 256, 256>>>(src, out);
}

// round 17
// speedup vs baseline: 1.1161x; 1.1161x over previous
#include <cuda_runtime.h>
#include <cuda_fp16.h>
#include <math.h>
#include <stdint.h>

#define N_NODES   50000
#define N_EDGES   800000
#define IN_DIM    128
#define OUT_DIM   64
#define NEG_SLOPE 0.01f

// ---------------- scratch (static device globals; no allocation) ------------
__device__ __align__(16) uint32_t g_zh[N_NODES * 32];  // z rows as half2 pairs (128B/row)
__device__ __align__(16) float    g_w[N_EDGES];        // per-edge exp(lrelu(e))
__device__ __align__(16) uint32_t g_wfrag[8 * 8 * 32 * 2];  // fp16 B fragments (4096 u32)
__device__ float g_s[N_NODES];             // z[n] . a_src
__device__ float g_d[N_NODES];             // z[n] . a_dst
__device__ int   g_rs[N_NODES + 1];        // row_start per dst node (dst sorted)

__device__ __forceinline__ float2 h2f2(uint32_t u) {
    return __half22float2(*(const __half2*)&u);
}
__device__ __forceinline__ uint32_t pack_h2(float a, float b) {
    __half2 p = __floats2half2_rn(a, b);
    return *(uint32_t*)&p;
}

// ---------------------------------------------------------------------------
// K0: one-shot fp16 B-fragment build for mma.m16n8k16, 2048 threads.
// idx = (nt*8 + kt)*32 + lane; n = nt*8 + (lane>>2); tid = lane&3.
// b0 = {fw[n][kt*16+2*tid], fw[n][kt*16+2*tid+1]}
// b1 = {fw[n][kt*16+2*tid+8], fw[n][kt*16+2*tid+9]}
// ---------------------------------------------------------------------------
__global__ __launch_bounds__(256) void wfrag_build_kernel(const float* __restrict__ fw) {
    const int idx = blockIdx.x * blockDim.x + threadIdx.x;   // 0..2047
    if (idx >= 8 * 8 * 32) return;
    const int lane = idx & 31;
    const int kt   = (idx >> 5) & 7;
    const int nt   = idx >> 8;
    const int n  = nt * 8 + (lane >> 2);
    const int k0 = kt * 16 + 2 * (lane & 3);
    const float* r = fw + n * IN_DIM;
    uint2 p;
    p.x = pack_h2(r[k0],     r[k0 + 1]);
    p.y = pack_h2(r[k0 + 8], r[k0 + 9]);
    *(uint2*)&g_wfrag[2 * idx] = p;
}

// ---------------------------------------------------------------------------
// K1: z = h @ fc_w^T via fp16 mma.sync.m16n8k16 (fp32 accum); fused s/d;
// z stored fp16. BM=128 -> 391 blocks, 8 warps; warp w owns rows w*16..+15
// x all 64 cols. K chunks of 16 (one k-tile per chunk), reg double-buffered.
// smem: 16 KB wfrag + 6 KB h chunk.
// ---------------------------------------------------------------------------
#define GEMM_BM 128
#define HSW 12   // hs row stride in u32 (8 + 4 pad): conflict-free LDS

__global__ __launch_bounds__(256) void gemm_sd_kernel(const float* __restrict__ h,
                                                      const float* __restrict__ attn_w) {
    __shared__ uint32_t wfrag[8 * 8 * 32 * 2];   // 16 KB (1024 uint4)
    __shared__ uint32_t hs[GEMM_BM * HSW];       // 6 KB: h chunk as half2
    __shared__ float a_srcs[OUT_DIM];
    __shared__ float a_dsts[OUT_DIM];

    const int t    = threadIdx.x;
    const int wid  = t >> 5;
    const int lane = t & 31;
    const int gid  = lane >> 2;   // 0..7
    const int tid  = lane & 3;    // 0..3
    const int mrow = wid * 16;    // warp's row tile

    // coalesced wfrag copy: 1024 uint4 -> 4 per thread
#pragma unroll
    for (int i = 0; i < 4; i++) {
        int idx = i * 256 + t;
        ((uint4*)wfrag)[idx] = ((const uint4*)g_wfrag)[idx];
    }
    if (t < OUT_DIM)            a_srcs[t]           = attn_w[t];
    else if (t < 2 * OUT_DIM)   a_dsts[t - OUT_DIM] = attn_w[t];

    const int node0 = blockIdx.x * GEMM_BM;
    const int r0 = node0 + mrow + gid;
    const int r1 = r0 + 8;
    const bool v0 = (r0 < N_NODES);
    const bool v1 = (r1 < N_NODES);

    // staging slots: 128 rows x 16 k = 512 float4; thread owns slots t, t+256
    const int n_a = t >> 2,         kq_a = t & 3;
    const int n_b = (t + 256) >> 2, kq_b = (t + 256) & 3;
    const int gn_a = node0 + n_a,   gn_b = node0 + n_b;
    const bool va = (gn_a < N_NODES), vb = (gn_b < N_NODES);
    const float* pa = h + (size_t)gn_a * IN_DIM + kq_a * 4;
    const float* pb = h + (size_t)gn_b * IN_DIM + kq_b * 4;

    float4 bufa, bufb;
    bufa = va ? *(const float4*)(pa) : make_float4(0.f, 0.f, 0.f, 0.f);
    bufb = vb ? *(const float4*)(pb) : make_float4(0.f, 0.f, 0.f, 0.f);

    float acc[8][4];
#pragma unroll
    for (int nt = 0; nt < 8; nt++)
#pragma unroll
        for (int c = 0; c < 4; c++) acc[nt][c] = 0.f;

    // ---- K chunks of 16 = one m16n8k16 k-tile each --------------------------
#pragma unroll
    for (int kc = 0; kc < 8; kc++) {
        __syncthreads();   // prior chunk's LDS reads done before overwrite
        {   // store staged chunk as half2 pairs (STS.64)
            uint2 u;
            u.x = pack_h2(bufa.x, bufa.y);
            u.y = pack_h2(bufa.z, bufa.w);
            *(uint2*)&hs[n_a * HSW + kq_a * 2] = u;
            u.x = pack_h2(bufb.x, bufb.y);
            u.y = pack_h2(bufb.z, bufb.w);
            *(uint2*)&hs[n_b * HSW + kq_b * 2] = u;
        }
        __syncthreads();
        if (kc < 7) {   // prefetch next chunk; hides under mma below
            const int kb = (kc + 1) * 16;
            bufa = va ? *(const float4*)(pa + kb) : make_float4(0.f, 0.f, 0.f, 0.f);
            bufb = vb ? *(const float4*)(pb + kb) : make_float4(0.f, 0.f, 0.f, 0.f);
        }

        // A fragments: scalar LDS, conflict-free (stride 12)
        uint32_t a0 = hs[(mrow + gid)     * HSW + tid];
        uint32_t a1 = hs[(mrow + gid + 8) * HSW + tid];
        uint32_t a2 = hs[(mrow + gid)     * HSW + tid + 4];
        uint32_t a3 = hs[(mrow + gid + 8) * HSW + tid + 4];
#pragma unroll
        for (int nt = 0; nt < 8; nt++) {
            int base = ((nt * 8 + kc) * 32 + lane) * 2;
            uint32_t b0 = wfrag[base];
            uint32_t b1 = wfrag[base + 1];
            asm volatile(
                "mma.sync.aligned.m16n8k16.row.col.f32.f16.f16.f32 "
                "{%0,%1,%2,%3}, {%4,%5,%6,%7}, {%8,%9}, {%0,%1,%2,%3};"
                : "+f"(acc[nt][0]), "+f"(acc[nt][1]),
                  "+f"(acc[nt][2]), "+f"(acc[nt][3])
                : "r"(a0), "r"(a1), "r"(a2), "r"(a3), "r"(b0), "r"(b1));
        }
    }

    // ---- epilogue: store z (fp16) + fused s/d (quad reduce) -----------------
    float s0 = 0.f, d0 = 0.f, s1 = 0.f, d1 = 0.f;
#pragma unroll
    for (int nt = 0; nt < 8; nt++) {
        int col = nt * 8 + tid * 2;
        if (v0) g_zh[(size_t)r0 * 32 + (col >> 1)] = pack_h2(acc[nt][0], acc[nt][1]);
        if (v1) g_zh[(size_t)r1 * 32 + (col >> 1)] = pack_h2(acc[nt][2], acc[nt][3]);
        float as0 = a_srcs[col], as1 = a_srcs[col + 1];
        float ad0 = a_dsts[col], ad1 = a_dsts[col + 1];
        s0 += acc[nt][0] * as0 + acc[nt][1] * as1;
        d0 += acc[nt][0] * ad0 + acc[nt][1] * ad1;
        s1 += acc[nt][2] * as0 + acc[nt][3] * as1;
        d1 += acc[nt][2] * ad0 + acc[nt][3] * ad1;
    }
#pragma unroll
    for (int o = 1; o <= 2; o <<= 1) {
        s0 += __shfl_xor_sync(0xffffffffu, s0, o);
        d0 += __shfl_xor_sync(0xffffffffu, d0, o);
        s1 += __shfl_xor_sync(0xffffffffu, s1, o);
        d1 += __shfl_xor_sync(0xffffffffu, d1, o);
    }
    if (tid == 0) {
        if (v0) { g_s[r0] = s0; g_d[r0] = d0; }
        if (v1) { g_s[r1] = s1; g_d[r1] = d1; }
    }
}

// ---------------------------------------------------------------------------
// K2: fused edge-weight precompute + rowstart scan. 4 edges/thread.
// ---------------------------------------------------------------------------
#define WR_EPT     4
#define WR_THREADS (N_EDGES / WR_EPT)   // 200000

__global__ __launch_bounds__(256) void wgt_rs_kernel(const int* __restrict__ src,
                                                     const int* __restrict__ dst) {
    const int gtid = blockIdx.x * blockDim.x + threadIdx.x;
    if (gtid >= WR_THREADS) return;
    const int i0 = gtid * WR_EPT;

    int4 s4 = *(const int4*)(src + i0);
    int4 d4 = *(const int4*)(dst + i0);

    float4 w;
    {
        float e0 = g_s[s4.x] + g_d[d4.x]; e0 = (e0 > 0.f) ? e0 : NEG_SLOPE * e0;
        float e1 = g_s[s4.y] + g_d[d4.y]; e1 = (e1 > 0.f) ? e1 : NEG_SLOPE * e1;
        float e2 = g_s[s4.z] + g_d[d4.z]; e2 = (e2 > 0.f) ? e2 : NEG_SLOPE * e2;
        float e3 = g_s[s4.w] + g_d[d4.w]; e3 = (e3 > 0.f) ? e3 : NEG_SLOPE * e3;
        w = make_float4(__expf(e0), __expf(e1), __expf(e2), __expf(e3));
    }
    *(float4*)(g_w + i0) = w;

    int prev = __shfl_up_sync(0xffffffffu, d4.w, 1);
    if ((threadIdx.x & 31) == 0) prev = (i0 == 0) ? -1 : dst[i0 - 1];

    int p = prev;
    int dk[4] = {d4.x, d4.y, d4.z, d4.w};
#pragma unroll
    for (int k = 0; k < WR_EPT; k++) {
        for (int n = p + 1; n <= dk[k]; n++) g_rs[n] = i0 + k;
        p = dk[k];
    }
    if (i0 + WR_EPT == N_EDGES) {
        for (int n = d4.w + 1; n <= N_NODES; n++) g_rs[n] = N_EDGES;
    }
}

// ---------------------------------------------------------------------------
// K4: aggregation, one warp per dst node, precomputed weights.
// 8-edge packets guard-free; one guarded tail packet. (Best measured form.)
// ---------------------------------------------------------------------------
__global__ __launch_bounds__(256) void edge_agg_kernel(const int* __restrict__ src,
                                                       float* __restrict__ out) {
    const int n    = (blockIdx.x * blockDim.x + threadIdx.x) >> 5;
    const int lane = threadIdx.x & 31;
    const int g    = lane >> 3;   // edge slot within packet
    const int q    = lane & 7;    // column quad: cols q*8 .. q*8+7
    if (n >= N_NODES) return;

    const int beg = g_rs[n], end = g_rs[n + 1];
    const uint4* zr = (const uint4*)g_zh;   // 8 uint4 per z row

    float acc[8];
#pragma unroll
    for (int c = 0; c < 8; c++) acc[c] = 0.f;
    float den = 0.f;

    int j = beg;
    const int full_end = beg + ((end - beg) & ~7);
    for (; j < full_end; j += 8) {
        const int e0 = j + g;
        const int e1 = j + 4 + g;
        const float w0 = g_w[e0];
        const float w1 = g_w[e1];
        const int   s0 = __ldg(&src[e0]);
        const int   s1 = __ldg(&src[e1]);

        uint4 A = zr[(size_t)s0 * 8 + q];
        uint4 B = zr[(size_t)s1 * 8 + q];
        float2 f;
        f = h2f2(A.x); acc[0] += w0 * f.x; acc[1] += w0 * f.y;
        f = h2f2(A.y); acc[2] += w0 * f.x; acc[3] += w0 * f.y;
        f = h2f2(A.z); acc[4] += w0 * f.x; acc[5] += w0 * f.y;
        f = h2f2(A.w); acc[6] += w0 * f.x; acc[7] += w0 * f.y;
        f = h2f2(B.x); acc[0] += w1 * f.x; acc[1] += w1 * f.y;
        f = h2f2(B.y); acc[2] += w1 * f.x; acc[3] += w1 * f.y;
        f = h2f2(B.z); acc[4] += w1 * f.x; acc[5] += w1 * f.y;
        f = h2f2(B.w); acc[6] += w1 * f.x; acc[7] += w1 * f.y;
        den += w0 + w1;
    }

    if (j < end) {
        const int e0 = j + g;
        const int e1 = j + 4 + g;
        const int i0 = min(e0, end - 1);
        const int i1 = min(e1, end - 1);
        const float w0 = (e0 < end) ? g_w[i0] : 0.f;
        const float w1 = (e1 < end) ? g_w[i1] : 0.f;
        const int   s0 = __ldg(&src[i0]);
        const int   s1 = __ldg(&src[i1]);

        uint4 A = zr[(size_t)s0 * 8 + q];
        uint4 B = zr[(size_t)s1 * 8 + q];
        float2 f;
        f = h2f2(A.x); acc[0] += w0 * f.x; acc[1] += w0 * f.y;
        f = h2f2(A.y); acc[2] += w0 * f.x; acc[3] += w0 * f.y;
        f = h2f2(A.z); acc[4] += w0 * f.x; acc[5] += w0 * f.y;
        f = h2f2(A.w); acc[6] += w0 * f.x; acc[7] += w0 * f.y;
        f = h2f2(B.x); acc[0] += w1 * f.x; acc[1] += w1 * f.y;
        f = h2f2(B.y); acc[2] += w1 * f.x; acc[3] += w1 * f.y;
        f = h2f2(B.z); acc[4] += w1 * f.x; acc[5] += w1 * f.y;
        f = h2f2(B.w); acc[6] += w1 * f.x; acc[7] += w1 * f.y;
        den += w0 + w1;
    }

#pragma unroll
    for (int c = 0; c < 8; c++) {
        acc[c] += __shfl_xor_sync(0xffffffffu, acc[c], 8);
        acc[c] += __shfl_xor_sync(0xffffffffu, acc[c], 16);
    }
    den += __shfl_xor_sync(0xffffffffu, den, 8);
    den += __shfl_xor_sync(0xffffffffu, den, 16);

    if (g == 0) {
        const float inv = (end > beg) ? 1.f / den : 0.f;
        float4* out4 = (float4*)out;
        out4[(size_t)n * 16 + q * 2]     =
            make_float4(acc[0] * inv, acc[1] * inv, acc[2] * inv, acc[3] * inv);
        out4[(size_t)n * 16 + q * 2 + 1] =
            make_float4(acc[4] * inv, acc[5] * inv, acc[6] * inv, acc[7] * inv);
    }
}

// ---------------------------------------------------------------------------
extern "C" void kernel_launch(void* const* d_in, const int* in_sizes, int n_in,
                              void* d_out, int out_size) {
    const float* h      = (const float*)d_in[0];
    const int*   src    = (const int*)d_in[1];
    const int*   dst    = (const int*)d_in[2];
    const float* fc_w   = (const float*)d_in[3];
    const float* attn_w = (const float*)d_in[4];
    float*       out    = (float*)d_out;

    (void)in_sizes; (void)n_in; (void)out_size;

    wfrag_build_kernel<<<8, 256>>>(fc_w);
    gemm_sd_kernel<<<(N_NODES + GEMM_BM - 1) / GEMM_BM, 256>>>(h, attn_w);
    wgt_rs_kernel<<<(WR_THREADS + 255) / 256, 256>>>(src, dst);
    edge_agg_kernel<<<(N_NODES * 32 + 255) / 256, 256>>>(src, out);
}